// round 10
// baseline (speedup 1.0000x reference)
#include <cuda_runtime.h>
#include <cuda_bf16.h>

#define N 1024
#define D 128
#define H 128

// Scratch (allocation-free rule: __device__ globals)
__device__ __align__(16) float g_v[D];   // reduced v
__device__ float g_nb[N];                // node_part[j] + consts

// ---------------------------------------------------------------------------
// Prologue (fused setup + nodepart). 32 blocks x 1024 threads.
// Each block computes u,v,consts (48 loads/thread, shared-reduced), then ALL
// 32 warps compute nb[j] for rows j = blk*32 + w. Block 0 writes g_v.
// ---------------------------------------------------------------------------
__global__ void __launch_bounds__(1024, 1)
prologue_kernel(const float* __restrict__ node_feat,
                const float* __restrict__ Wh,
                const float* __restrict__ bh,
                const float* __restrict__ Wt,
                const float* __restrict__ bt,
                const float* __restrict__ Wr,
                const float* __restrict__ br,
                const float* __restrict__ wt_w,
                const float* __restrict__ wt_b) {
    const int tid  = threadIdx.x;
    const int d    = tid & 127;
    const int g    = tid >> 7;      // 0..7
    const int lane = tid & 31;
    const int w    = tid >> 5;      // warp 0..31

    __shared__ float su[8][128];
    __shared__ float sv[8][128];
    __shared__ float sconsts;

    float u = 0.f, v = 0.f;
    const int h0 = g * 16;
    #pragma unroll
    for (int k = 0; k < 16; ++k) {
        int h = h0 + k;
        float w1 = __ldg(&wt_w[h]);
        float w2 = __ldg(&wt_w[H + h]);
        float w3 = __ldg(&wt_w[2 * H + h]);
        u = fmaf(__ldg(&Wh[h * D + d]), w1, u);
        u = fmaf(__ldg(&Wt[h * D + d]), w2, u);
        v = fmaf(__ldg(&Wr[h * D + d]), w3, v);
    }
    su[g][d] = u;
    sv[g][d] = v;

    if (tid < 32) {
        float c = 0.f;
        #pragma unroll
        for (int h = lane; h < H; h += 32) {
            c += bh[h] * __ldg(&wt_w[h]) + bt[h] * __ldg(&wt_w[H + h]) +
                 br[h] * __ldg(&wt_w[2 * H + h]);
        }
        #pragma unroll
        for (int o = 16; o > 0; o >>= 1) c += __shfl_xor_sync(0xffffffffu, c, o);
        if (lane == 0) sconsts = c + __ldg(&wt_b[0]);
    }
    __syncthreads();

    if (blockIdx.x == 0 && tid < 128) {
        float vv = 0.f;
        #pragma unroll
        for (int gg = 0; gg < 8; ++gg) vv += sv[gg][tid];
        g_v[tid] = vv;
    }

    // all 32 warps: nb[j] for j = blk*32 + w
    {
        const int j = blockIdx.x * 32 + w;
        float4 u4 = make_float4(0.f, 0.f, 0.f, 0.f);
        #pragma unroll
        for (int gg = 0; gg < 8; ++gg) {
            float4 p = reinterpret_cast<const float4*>(su[gg])[lane];
            u4.x += p.x; u4.y += p.y; u4.z += p.z; u4.w += p.w;
        }
        float4 x = reinterpret_cast<const float4*>(node_feat + (size_t)j * D)[lane];
        float dsum = x.x * u4.x + x.y * u4.y + x.z * u4.z + x.w * u4.w;
        #pragma unroll
        for (int o = 16; o > 0; o >>= 1)
            dsum += __shfl_xor_sync(0xffffffffu, dsum, o);
        if (lane == 0) g_nb[j] = dsum + sconsts;
    }
}

// Merge two distributed partial sums: lanes with (lane&bit)==0 end up with
// the pair-sum of 'a', lanes with bit set get the pair-sum of 'b'.
__device__ __forceinline__ float merge2(float a, float b, int lane, int bit) {
    float t = (lane & bit) ? a : b;
    float u = __shfl_xor_sync(0xffffffffu, t, bit);
    return ((lane & bit) ? b : a) + u;
}

// ---------------------------------------------------------------------------
// Main: one block per row, 512 threads, 2 blocks resident per SM so block B
// streams while block A drains/epilogues/exits (hides the boundary bubble
// that capped DRAM at ~84% with 1024-thread blocks).
// Warp w owns j in [w*64, w*64+64), 8 batches of 8. Merge-tree reduction
// (9 SHFL/batch). Single-barrier epilogue.
// ---------------------------------------------------------------------------
__global__ void __launch_bounds__(512, 2)
main_kernel(const float* __restrict__ edge_feat, float* __restrict__ out) {
    const int i    = blockIdx.x;
    const int tid  = threadIdx.x;
    const int lane = tid & 31;
    const int w    = tid >> 5;      // 0..15

    __shared__ float sp[N];      // exp(energy)
    __shared__ float sred[16];

    const float4 v4 = reinterpret_cast<const float4*>(g_v)[lane];
    const float4* base =
        reinterpret_cast<const float4*>(edge_feat + (size_t)i * N * D);

    const int j0 = w << 6;                     // 64 j's per warp
    const float nbv0 = g_nb[j0 + lane];        // nb for j0..j0+31
    const float nbv1 = g_nb[j0 + 32 + lane];   // nb for j0+32..j0+63
    const int idx = (((lane >> 2) & 1) << 2) | (((lane >> 3) & 1) << 1)
                  | ((lane >> 4) & 1);

    float wsum = 0.f;
    #pragma unroll
    for (int k = 0; k < 64; k += 8) {
        float4 x0 = __ldcs(&base[(size_t)(j0 + k + 0) * (D / 4) + lane]);
        float4 x1 = __ldcs(&base[(size_t)(j0 + k + 1) * (D / 4) + lane]);
        float4 x2 = __ldcs(&base[(size_t)(j0 + k + 2) * (D / 4) + lane]);
        float4 x3 = __ldcs(&base[(size_t)(j0 + k + 3) * (D / 4) + lane]);
        float4 x4 = __ldcs(&base[(size_t)(j0 + k + 4) * (D / 4) + lane]);
        float4 x5 = __ldcs(&base[(size_t)(j0 + k + 5) * (D / 4) + lane]);
        float4 x6 = __ldcs(&base[(size_t)(j0 + k + 6) * (D / 4) + lane]);
        float4 x7 = __ldcs(&base[(size_t)(j0 + k + 7) * (D / 4) + lane]);
        float d0 = x0.x * v4.x + x0.y * v4.y + x0.z * v4.z + x0.w * v4.w;
        float d1 = x1.x * v4.x + x1.y * v4.y + x1.z * v4.z + x1.w * v4.w;
        float d2 = x2.x * v4.x + x2.y * v4.y + x2.z * v4.z + x2.w * v4.w;
        float d3 = x3.x * v4.x + x3.y * v4.y + x3.z * v4.z + x3.w * v4.w;
        float d4 = x4.x * v4.x + x4.y * v4.y + x4.z * v4.z + x4.w * v4.w;
        float d5 = x5.x * v4.x + x5.y * v4.y + x5.z * v4.z + x5.w * v4.w;
        float d6 = x6.x * v4.x + x6.y * v4.y + x6.z * v4.z + x6.w * v4.w;
        float d7 = x7.x * v4.x + x7.y * v4.y + x7.z * v4.z + x7.w * v4.w;

        // merge tree: 8 values -> 1 per lane group. 9 SHFLs total.
        float e0 = merge2(d0, d1, lane, 16);
        float e1 = merge2(d2, d3, lane, 16);
        float e2 = merge2(d4, d5, lane, 16);
        float e3 = merge2(d6, d7, lane, 16);
        float f0 = merge2(e0, e1, lane, 8);
        float f1 = merge2(e2, e3, lane, 8);
        float gg = merge2(f0, f1, lane, 4);
        gg += __shfl_xor_sync(0xffffffffu, gg, 2);
        gg += __shfl_xor_sync(0xffffffffu, gg, 1);
        // lane holds full dot for j = j0 + k + idx (4 lanes per value)

        float nbsrc = (k < 32) ? nbv0 : nbv1;
        float nb = __shfl_sync(0xffffffffu, nbsrc, (k + idx) & 31);
        float p  = __expf(gg + nb);
        if ((lane & 3) == 0) {
            sp[j0 + k + idx] = p;
            wsum += p;
        }
    }
    #pragma unroll
    for (int o = 16; o > 0; o >>= 1)
        wsum += __shfl_xor_sync(0xffffffffu, wsum, o);
    if (lane == 0) sred[w] = wsum;
    __syncthreads();   // single barrier

    float ss = (lane < 16) ? sred[lane] : 0.f;
    #pragma unroll
    for (int o = 16; o > 0; o >>= 1)
        ss += __shfl_xor_sync(0xffffffffu, ss, o);

    const float inv = 1.0f / ss;
    out[(size_t)i * N + tid]       = sp[tid] * inv;
    out[(size_t)i * N + tid + 512] = sp[tid + 512] * inv;
}

// ---------------------------------------------------------------------------
// Launcher. Input order per metadata:
// 0 node_feat (N,D) f32 | 1 edge_feat (N,N,D) f32 | 2 mask (unused)
// 3 Wh | 4 bh | 5 Wt | 6 bt | 7 Wr | 8 br | 9 wt_w | 10 wt_b
// ---------------------------------------------------------------------------
extern "C" void kernel_launch(void* const* d_in, const int* in_sizes, int n_in,
                              void* d_out, int out_size) {
    const float* node_feat = (const float*)d_in[0];
    const float* edge_feat = (const float*)d_in[1];
    const float* Wh   = (const float*)d_in[3];
    const float* bh   = (const float*)d_in[4];
    const float* Wt   = (const float*)d_in[5];
    const float* bt   = (const float*)d_in[6];
    const float* Wr   = (const float*)d_in[7];
    const float* br   = (const float*)d_in[8];
    const float* wt_w = (const float*)d_in[9];
    const float* wt_b = (const float*)d_in[10];
    float* out = (float*)d_out;

    prologue_kernel<<<32, 1024>>>(node_feat, Wh, bh, Wt, bt, Wr, br, wt_w, wt_b);
    main_kernel<<<N, 512>>>(edge_feat, out);
}

// round 11
// speedup vs baseline: 1.0664x; 1.0664x over previous
#include <cuda_runtime.h>
#include <cuda_bf16.h>

#define N 1024
#define D 128
#define H 128

// Scratch (allocation-free rule: __device__ globals)
__device__ __align__(16) float g_v[D];   // reduced v
__device__ float g_nb[N];                // node_part[j] + consts

// ---------------------------------------------------------------------------
// Prologue (fused setup + nodepart). 128 blocks x 1024 threads.
// (R9-verified config: ~5.2us including launch gap.)
// ---------------------------------------------------------------------------
__global__ void __launch_bounds__(1024, 1)
prologue_kernel(const float* __restrict__ node_feat,
                const float* __restrict__ Wh,
                const float* __restrict__ bh,
                const float* __restrict__ Wt,
                const float* __restrict__ bt,
                const float* __restrict__ Wr,
                const float* __restrict__ br,
                const float* __restrict__ wt_w,
                const float* __restrict__ wt_b) {
    const int tid  = threadIdx.x;
    const int d    = tid & 127;
    const int g    = tid >> 7;      // 0..7
    const int lane = tid & 31;
    const int w    = tid >> 5;      // warp 0..31

    __shared__ float su[8][128];
    __shared__ float sv[8][128];
    __shared__ float sconsts;

    float u = 0.f, v = 0.f;
    const int h0 = g * 16;
    #pragma unroll
    for (int k = 0; k < 16; ++k) {
        int h = h0 + k;
        float w1 = __ldg(&wt_w[h]);
        float w2 = __ldg(&wt_w[H + h]);
        float w3 = __ldg(&wt_w[2 * H + h]);
        u = fmaf(__ldg(&Wh[h * D + d]), w1, u);
        u = fmaf(__ldg(&Wt[h * D + d]), w2, u);
        v = fmaf(__ldg(&Wr[h * D + d]), w3, v);
    }
    su[g][d] = u;
    sv[g][d] = v;

    if (tid < 32) {
        float c = 0.f;
        #pragma unroll
        for (int h = lane; h < H; h += 32) {
            c += bh[h] * __ldg(&wt_w[h]) + bt[h] * __ldg(&wt_w[H + h]) +
                 br[h] * __ldg(&wt_w[2 * H + h]);
        }
        #pragma unroll
        for (int o = 16; o > 0; o >>= 1) c += __shfl_xor_sync(0xffffffffu, c, o);
        if (lane == 0) sconsts = c + __ldg(&wt_b[0]);
    }
    __syncthreads();

    if (blockIdx.x == 0 && tid < 128) {
        float vv = 0.f;
        #pragma unroll
        for (int gg = 0; gg < 8; ++gg) vv += sv[gg][tid];
        g_v[tid] = vv;
    }

    if (w < 8) {
        const int j = blockIdx.x * 8 + w;
        float4 u4 = make_float4(0.f, 0.f, 0.f, 0.f);
        #pragma unroll
        for (int gg = 0; gg < 8; ++gg) {
            float4 p = reinterpret_cast<const float4*>(su[gg])[lane];
            u4.x += p.x; u4.y += p.y; u4.z += p.z; u4.w += p.w;
        }
        float4 x = reinterpret_cast<const float4*>(node_feat + (size_t)j * D)[lane];
        float dsum = x.x * u4.x + x.y * u4.y + x.z * u4.z + x.w * u4.w;
        #pragma unroll
        for (int o = 16; o > 0; o >>= 1)
            dsum += __shfl_xor_sync(0xffffffffu, dsum, o);
        if (lane == 0) g_nb[j] = dsum + sconsts;
    }
}

// Merge two distributed partial sums: lanes with (lane&bit)==0 end up with
// the pair-sum of 'a', lanes with bit set get the pair-sum of 'b'.
__device__ __forceinline__ float merge2(float a, float b, int lane, int bit) {
    float t = (lane & bit) ? a : b;
    float u = __shfl_xor_sync(0xffffffffu, t, bit);
    return ((lane & bit) ? b : a) + u;
}

// One 8-j batch for row base pointer `base`: load, dot, merge-tree, exp,
// conditional store + accumulate. Identical math to R9.
__device__ __forceinline__ void do_batch(const float4* __restrict__ base,
                                         float4 v4, int j0, int k, int lane,
                                         int idx, float nbv,
                                         float* __restrict__ spb,
                                         float& wsum) {
    float4 x0 = __ldcs(&base[(size_t)(j0 + k + 0) * (D / 4) + lane]);
    float4 x1 = __ldcs(&base[(size_t)(j0 + k + 1) * (D / 4) + lane]);
    float4 x2 = __ldcs(&base[(size_t)(j0 + k + 2) * (D / 4) + lane]);
    float4 x3 = __ldcs(&base[(size_t)(j0 + k + 3) * (D / 4) + lane]);
    float4 x4 = __ldcs(&base[(size_t)(j0 + k + 4) * (D / 4) + lane]);
    float4 x5 = __ldcs(&base[(size_t)(j0 + k + 5) * (D / 4) + lane]);
    float4 x6 = __ldcs(&base[(size_t)(j0 + k + 6) * (D / 4) + lane]);
    float4 x7 = __ldcs(&base[(size_t)(j0 + k + 7) * (D / 4) + lane]);
    float d0 = x0.x * v4.x + x0.y * v4.y + x0.z * v4.z + x0.w * v4.w;
    float d1 = x1.x * v4.x + x1.y * v4.y + x1.z * v4.z + x1.w * v4.w;
    float d2 = x2.x * v4.x + x2.y * v4.y + x2.z * v4.z + x2.w * v4.w;
    float d3 = x3.x * v4.x + x3.y * v4.y + x3.z * v4.z + x3.w * v4.w;
    float d4 = x4.x * v4.x + x4.y * v4.y + x4.z * v4.z + x4.w * v4.w;
    float d5 = x5.x * v4.x + x5.y * v4.y + x5.z * v4.z + x5.w * v4.w;
    float d6 = x6.x * v4.x + x6.y * v4.y + x6.z * v4.z + x6.w * v4.w;
    float d7 = x7.x * v4.x + x7.y * v4.y + x7.z * v4.z + x7.w * v4.w;

    float e0 = merge2(d0, d1, lane, 16);
    float e1 = merge2(d2, d3, lane, 16);
    float e2 = merge2(d4, d5, lane, 16);
    float e3 = merge2(d6, d7, lane, 16);
    float f0 = merge2(e0, e1, lane, 8);
    float f1 = merge2(e2, e3, lane, 8);
    float gg = merge2(f0, f1, lane, 4);
    gg += __shfl_xor_sync(0xffffffffu, gg, 2);
    gg += __shfl_xor_sync(0xffffffffu, gg, 1);

    float nb = __shfl_sync(0xffffffffu, nbv, k + idx);
    float p  = __expf(gg + nb);
    if ((lane & 3) == 0) {
        spb[j0 + k + idx] = p;
        wsum += p;
    }
}

// ---------------------------------------------------------------------------
// Main: TWO rows per block, 1024 threads, 1 block/SM (the verified-fast
// residency). Row B's batches are independent of row A's reduction tree, so
// B's loads issue while A drains — and there is only ONE barrier + epilogue
// per 2 rows, halving block-boundary bubbles (512 blocks, 3.5 waves).
// ---------------------------------------------------------------------------
__global__ void __launch_bounds__(1024, 1)
main_kernel(const float* __restrict__ edge_feat, float* __restrict__ out) {
    const int tid  = threadIdx.x;
    const int lane = tid & 31;
    const int w    = tid >> 5;

    __shared__ float sp[2][N];   // exp(energy) for rows A,B
    __shared__ float sredA[32];
    __shared__ float sredB[32];

    const int rowA = blockIdx.x * 2;
    const int rowB = rowA + 1;

    const float4 v4 = reinterpret_cast<const float4*>(g_v)[lane];
    const float4* baseA =
        reinterpret_cast<const float4*>(edge_feat + (size_t)rowA * N * D);
    const float4* baseB =
        reinterpret_cast<const float4*>(edge_feat + (size_t)rowB * N * D);

    const int j0 = w << 5;
    const float nbv = g_nb[j0 + lane];
    const int idx = (((lane >> 2) & 1) << 2) | (((lane >> 3) & 1) << 1)
                  | ((lane >> 4) & 1);

    float wsumA = 0.f, wsumB = 0.f;
    #pragma unroll
    for (int k = 0; k < 32; k += 8)
        do_batch(baseA, v4, j0, k, lane, idx, nbv, sp[0], wsumA);
    #pragma unroll
    for (int k = 0; k < 32; k += 8)
        do_batch(baseB, v4, j0, k, lane, idx, nbv, sp[1], wsumB);

    #pragma unroll
    for (int o = 16; o > 0; o >>= 1) {
        wsumA += __shfl_xor_sync(0xffffffffu, wsumA, o);
        wsumB += __shfl_xor_sync(0xffffffffu, wsumB, o);
    }
    if (lane == 0) { sredA[w] = wsumA; sredB[w] = wsumB; }
    __syncthreads();   // single barrier for both rows

    float sa = sredA[lane];
    float sb = sredB[lane];
    #pragma unroll
    for (int o = 16; o > 0; o >>= 1) {
        sa += __shfl_xor_sync(0xffffffffu, sa, o);
        sb += __shfl_xor_sync(0xffffffffu, sb, o);
    }

    out[(size_t)rowA * N + tid] = sp[0][tid] * (1.0f / sa);
    out[(size_t)rowB * N + tid] = sp[1][tid] * (1.0f / sb);
}

// ---------------------------------------------------------------------------
// Launcher. Input order per metadata:
// 0 node_feat (N,D) f32 | 1 edge_feat (N,N,D) f32 | 2 mask (unused)
// 3 Wh | 4 bh | 5 Wt | 6 bt | 7 Wr | 8 br | 9 wt_w | 10 wt_b
// ---------------------------------------------------------------------------
extern "C" void kernel_launch(void* const* d_in, const int* in_sizes, int n_in,
                              void* d_out, int out_size) {
    const float* node_feat = (const float*)d_in[0];
    const float* edge_feat = (const float*)d_in[1];
    const float* Wh   = (const float*)d_in[3];
    const float* bh   = (const float*)d_in[4];
    const float* Wt   = (const float*)d_in[5];
    const float* bt   = (const float*)d_in[6];
    const float* Wr   = (const float*)d_in[7];
    const float* br   = (const float*)d_in[8];
    const float* wt_w = (const float*)d_in[9];
    const float* wt_b = (const float*)d_in[10];
    float* out = (float*)d_out;

    prologue_kernel<<<128, 1024>>>(node_feat, Wh, bh, Wt, bt, Wr, br, wt_w, wt_b);
    main_kernel<<<N / 2, 1024>>>(edge_feat, out);
}

// round 12
// speedup vs baseline: 1.1152x; 1.0458x over previous
#include <cuda_runtime.h>
#include <cuda_bf16.h>

#define N 1024
#define D 128
#define H 128

// Scratch (allocation-free rule: __device__ globals)
__device__ __align__(16) float g_v[D];   // reduced v
__device__ float g_nb[N];                // node_part[j] (consts dropped: softmax shift-invariant)

// ---------------------------------------------------------------------------
// Prologue (fused setup + nodepart). 128 blocks x 1024 threads.
// vs R9: consts computation removed entirely (cancels in softmax), and each
// nb-warp's node_feat row is prefetched BEFORE the weight-load chain so its
// DRAM round overlaps the weight loads.
// ---------------------------------------------------------------------------
__global__ void __launch_bounds__(1024, 1)
prologue_kernel(const float* __restrict__ node_feat,
                const float* __restrict__ Wh,
                const float* __restrict__ Wt,
                const float* __restrict__ Wr,
                const float* __restrict__ wt_w) {
    const int tid  = threadIdx.x;
    const int d    = tid & 127;
    const int g    = tid >> 7;      // 0..7
    const int lane = tid & 31;
    const int w    = tid >> 5;      // warp 0..31

    __shared__ float su[8][128];
    __shared__ float sv[8][128];

    // prefetch node_feat row for nb warps (independent of weight loads)
    float4 x = make_float4(0.f, 0.f, 0.f, 0.f);
    const int j = blockIdx.x * 8 + w;
    if (w < 8) {
        x = reinterpret_cast<const float4*>(node_feat + (size_t)j * D)[lane];
    }

    float u = 0.f, v = 0.f;
    const int h0 = g * 16;
    #pragma unroll
    for (int k = 0; k < 16; ++k) {
        int h = h0 + k;
        float w1 = __ldg(&wt_w[h]);
        float w2 = __ldg(&wt_w[H + h]);
        float w3 = __ldg(&wt_w[2 * H + h]);
        u = fmaf(__ldg(&Wh[h * D + d]), w1, u);
        u = fmaf(__ldg(&Wt[h * D + d]), w2, u);
        v = fmaf(__ldg(&Wr[h * D + d]), w3, v);
    }
    su[g][d] = u;
    sv[g][d] = v;
    __syncthreads();

    if (blockIdx.x == 0 && tid < 128) {
        float vv = 0.f;
        #pragma unroll
        for (int gg = 0; gg < 8; ++gg) vv += sv[gg][tid];
        g_v[tid] = vv;
    }

    if (w < 8) {
        float4 u4 = make_float4(0.f, 0.f, 0.f, 0.f);
        #pragma unroll
        for (int gg = 0; gg < 8; ++gg) {
            float4 p = reinterpret_cast<const float4*>(su[gg])[lane];
            u4.x += p.x; u4.y += p.y; u4.z += p.z; u4.w += p.w;
        }
        float dsum = x.x * u4.x + x.y * u4.y + x.z * u4.z + x.w * u4.w;
        #pragma unroll
        for (int o = 16; o > 0; o >>= 1)
            dsum += __shfl_xor_sync(0xffffffffu, dsum, o);
        if (lane == 0) g_nb[j] = dsum;
    }
}

// Merge two distributed partial sums: lanes with (lane&bit)==0 end up with
// the pair-sum of 'a', lanes with bit set get the pair-sum of 'b'.
__device__ __forceinline__ float merge2(float a, float b, int lane, int bit) {
    float t = (lane & bit) ? a : b;
    float u = __shfl_xor_sync(0xffffffffu, t, bit);
    return ((lane & bit) ? b : a) + u;
}

// ---------------------------------------------------------------------------
// Main: R9-verified optimum (81.3us @ 84.2% DRAM). One block per row,
// 1024 threads, 1 block/SM, grid=1024 (6.92 waves, near-perfect tail).
// Warp w owns j in [w*32, w*32+32), unroll 8. Merge-tree reduction
// (9 SHFL/batch). Single-barrier epilogue.
// ---------------------------------------------------------------------------
__global__ void __launch_bounds__(1024, 1)
main_kernel(const float* __restrict__ edge_feat, float* __restrict__ out) {
    const int i    = blockIdx.x;
    const int tid  = threadIdx.x;
    const int lane = tid & 31;
    const int w    = tid >> 5;

    __shared__ float sp[N];      // exp(energy)
    __shared__ float sred[32];

    const float4 v4 = reinterpret_cast<const float4*>(g_v)[lane];
    const float4* base =
        reinterpret_cast<const float4*>(edge_feat + (size_t)i * N * D);

    const int j0 = w << 5;
    const float nbv = g_nb[j0 + lane];   // this warp's 32 nb values, coalesced
    const int idx = (((lane >> 2) & 1) << 2) | (((lane >> 3) & 1) << 1)
                  | ((lane >> 4) & 1);   // which d this lane ends up owning

    float wsum = 0.f;
    #pragma unroll
    for (int k = 0; k < 32; k += 8) {
        float4 x0 = __ldcs(&base[(size_t)(j0 + k + 0) * (D / 4) + lane]);
        float4 x1 = __ldcs(&base[(size_t)(j0 + k + 1) * (D / 4) + lane]);
        float4 x2 = __ldcs(&base[(size_t)(j0 + k + 2) * (D / 4) + lane]);
        float4 x3 = __ldcs(&base[(size_t)(j0 + k + 3) * (D / 4) + lane]);
        float4 x4 = __ldcs(&base[(size_t)(j0 + k + 4) * (D / 4) + lane]);
        float4 x5 = __ldcs(&base[(size_t)(j0 + k + 5) * (D / 4) + lane]);
        float4 x6 = __ldcs(&base[(size_t)(j0 + k + 6) * (D / 4) + lane]);
        float4 x7 = __ldcs(&base[(size_t)(j0 + k + 7) * (D / 4) + lane]);
        float d0 = x0.x * v4.x + x0.y * v4.y + x0.z * v4.z + x0.w * v4.w;
        float d1 = x1.x * v4.x + x1.y * v4.y + x1.z * v4.z + x1.w * v4.w;
        float d2 = x2.x * v4.x + x2.y * v4.y + x2.z * v4.z + x2.w * v4.w;
        float d3 = x3.x * v4.x + x3.y * v4.y + x3.z * v4.z + x3.w * v4.w;
        float d4 = x4.x * v4.x + x4.y * v4.y + x4.z * v4.z + x4.w * v4.w;
        float d5 = x5.x * v4.x + x5.y * v4.y + x5.z * v4.z + x5.w * v4.w;
        float d6 = x6.x * v4.x + x6.y * v4.y + x6.z * v4.z + x6.w * v4.w;
        float d7 = x7.x * v4.x + x7.y * v4.y + x7.z * v4.z + x7.w * v4.w;

        // merge tree: 8 values -> 1 per lane group. 9 SHFLs total.
        float e0 = merge2(d0, d1, lane, 16);
        float e1 = merge2(d2, d3, lane, 16);
        float e2 = merge2(d4, d5, lane, 16);
        float e3 = merge2(d6, d7, lane, 16);
        float f0 = merge2(e0, e1, lane, 8);
        float f1 = merge2(e2, e3, lane, 8);
        float gg = merge2(f0, f1, lane, 4);
        gg += __shfl_xor_sync(0xffffffffu, gg, 2);
        gg += __shfl_xor_sync(0xffffffffu, gg, 1);
        // lane now holds full dot for j = j0 + k + idx (4 lanes per value)

        float nb = __shfl_sync(0xffffffffu, nbv, k + idx);
        float p  = __expf(gg + nb);
        if ((lane & 3) == 0) {
            sp[j0 + k + idx] = p;
            wsum += p;
        }
    }
    // 8 storing lanes hold distinct values; others carry 0
    #pragma unroll
    for (int o = 16; o > 0; o >>= 1)
        wsum += __shfl_xor_sync(0xffffffffu, wsum, o);
    if (lane == 0) sred[w] = wsum;
    __syncthreads();   // single barrier

    float ss = sred[lane];
    #pragma unroll
    for (int o = 16; o > 0; o >>= 1)
        ss += __shfl_xor_sync(0xffffffffu, ss, o);

    out[(size_t)i * N + tid] = sp[tid] * (1.0f / ss);
}

// ---------------------------------------------------------------------------
// Launcher. Input order per metadata:
// 0 node_feat (N,D) f32 | 1 edge_feat (N,N,D) f32 | 2 mask (unused)
// 3 Wh | 4 bh | 5 Wt | 6 bt | 7 Wr | 8 br | 9 wt_w | 10 wt_b
// (bh/bt/br/wt_b unused: they shift all energies equally -> cancel in softmax)
// ---------------------------------------------------------------------------
extern "C" void kernel_launch(void* const* d_in, const int* in_sizes, int n_in,
                              void* d_out, int out_size) {
    const float* node_feat = (const float*)d_in[0];
    const float* edge_feat = (const float*)d_in[1];
    const float* Wh   = (const float*)d_in[3];
    const float* Wt   = (const float*)d_in[5];
    const float* Wr   = (const float*)d_in[7];
    const float* wt_w = (const float*)d_in[9];
    float* out = (float*)d_out;

    prologue_kernel<<<128, 1024>>>(node_feat, Wh, Wt, Wr, wt_w);
    main_kernel<<<N, 1024>>>(edge_feat, out);
}

// round 13
// speedup vs baseline: 1.1169x; 1.0015x over previous
#include <cuda_runtime.h>
#include <cuda_bf16.h>

#define N 1024
#define D 128
#define H 128

// Scratch (allocation-free rule: __device__ globals)
__device__ __align__(16) float g_v[D];   // reduced v
__device__ float g_nb[N];                // node_part[j] (consts dropped: softmax shift-invariant)

// ---------------------------------------------------------------------------
// Prologue (fused setup + nodepart). 64 blocks x 1024 threads.
// Halves the redundant weight traffic vs 128 blocks (12 MB through L2).
// Thread (g,d): g = tid>>7 covers h in [g*16, g*16+16). Warps 0..15 then
// compute nb[j] for rows j = blk*16 + w. Block 0 materializes g_v.
// node_feat rows prefetched before the weight chain (independent DRAM round).
// ---------------------------------------------------------------------------
__global__ void __launch_bounds__(1024, 1)
prologue_kernel(const float* __restrict__ node_feat,
                const float* __restrict__ Wh,
                const float* __restrict__ Wt,
                const float* __restrict__ Wr,
                const float* __restrict__ wt_w) {
    const int tid  = threadIdx.x;
    const int d    = tid & 127;
    const int g    = tid >> 7;      // 0..7
    const int lane = tid & 31;
    const int w    = tid >> 5;      // warp 0..31

    __shared__ float su[8][128];
    __shared__ float sv[8][128];

    // prefetch node_feat row for nb warps (independent of weight loads)
    float4 x = make_float4(0.f, 0.f, 0.f, 0.f);
    const int j = blockIdx.x * 16 + w;
    if (w < 16) {
        x = reinterpret_cast<const float4*>(node_feat + (size_t)j * D)[lane];
    }

    float u = 0.f, v = 0.f;
    const int h0 = g * 16;
    #pragma unroll
    for (int k = 0; k < 16; ++k) {
        int h = h0 + k;
        float w1 = __ldg(&wt_w[h]);
        float w2 = __ldg(&wt_w[H + h]);
        float w3 = __ldg(&wt_w[2 * H + h]);
        u = fmaf(__ldg(&Wh[h * D + d]), w1, u);
        u = fmaf(__ldg(&Wt[h * D + d]), w2, u);
        v = fmaf(__ldg(&Wr[h * D + d]), w3, v);
    }
    su[g][d] = u;
    sv[g][d] = v;
    __syncthreads();

    if (blockIdx.x == 0 && tid < 128) {
        float vv = 0.f;
        #pragma unroll
        for (int gg = 0; gg < 8; ++gg) vv += sv[gg][tid];
        g_v[tid] = vv;
    }

    if (w < 16) {
        float4 u4 = make_float4(0.f, 0.f, 0.f, 0.f);
        #pragma unroll
        for (int gg = 0; gg < 8; ++gg) {
            float4 p = reinterpret_cast<const float4*>(su[gg])[lane];
            u4.x += p.x; u4.y += p.y; u4.z += p.z; u4.w += p.w;
        }
        float dsum = x.x * u4.x + x.y * u4.y + x.z * u4.z + x.w * u4.w;
        #pragma unroll
        for (int o = 16; o > 0; o >>= 1)
            dsum += __shfl_xor_sync(0xffffffffu, dsum, o);
        if (lane == 0) g_nb[j] = dsum;
    }
}

// Merge two distributed partial sums: lanes with (lane&bit)==0 end up with
// the pair-sum of 'a', lanes with bit set get the pair-sum of 'b'.
__device__ __forceinline__ float merge2(float a, float b, int lane, int bit) {
    float t = (lane & bit) ? a : b;
    float u = __shfl_xor_sync(0xffffffffu, t, bit);
    return ((lane & bit) ? b : a) + u;
}

// ---------------------------------------------------------------------------
// Main: converged optimum (80.7us @ 84.8% DRAM, verified over 5 shape
// experiments). One block per row, 1024 threads, 1 block/SM, grid=1024
// (6.92 waves, near-perfect tail). Warp w owns j in [w*32, w*32+32),
// unroll 8. Merge-tree reduction (9 SHFL/batch). Single-barrier epilogue.
// Only change vs R12: __stcs on the output store (no L2 write-allocate
// pollution for data we never re-read).
// ---------------------------------------------------------------------------
__global__ void __launch_bounds__(1024, 1)
main_kernel(const float* __restrict__ edge_feat, float* __restrict__ out) {
    const int i    = blockIdx.x;
    const int tid  = threadIdx.x;
    const int lane = tid & 31;
    const int w    = tid >> 5;

    __shared__ float sp[N];      // exp(energy)
    __shared__ float sred[32];

    const float4 v4 = reinterpret_cast<const float4*>(g_v)[lane];
    const float4* base =
        reinterpret_cast<const float4*>(edge_feat + (size_t)i * N * D);

    const int j0 = w << 5;
    const float nbv = g_nb[j0 + lane];   // this warp's 32 nb values, coalesced
    const int idx = (((lane >> 2) & 1) << 2) | (((lane >> 3) & 1) << 1)
                  | ((lane >> 4) & 1);   // which d this lane ends up owning

    float wsum = 0.f;
    #pragma unroll
    for (int k = 0; k < 32; k += 8) {
        float4 x0 = __ldcs(&base[(size_t)(j0 + k + 0) * (D / 4) + lane]);
        float4 x1 = __ldcs(&base[(size_t)(j0 + k + 1) * (D / 4) + lane]);
        float4 x2 = __ldcs(&base[(size_t)(j0 + k + 2) * (D / 4) + lane]);
        float4 x3 = __ldcs(&base[(size_t)(j0 + k + 3) * (D / 4) + lane]);
        float4 x4 = __ldcs(&base[(size_t)(j0 + k + 4) * (D / 4) + lane]);
        float4 x5 = __ldcs(&base[(size_t)(j0 + k + 5) * (D / 4) + lane]);
        float4 x6 = __ldcs(&base[(size_t)(j0 + k + 6) * (D / 4) + lane]);
        float4 x7 = __ldcs(&base[(size_t)(j0 + k + 7) * (D / 4) + lane]);
        float d0 = x0.x * v4.x + x0.y * v4.y + x0.z * v4.z + x0.w * v4.w;
        float d1 = x1.x * v4.x + x1.y * v4.y + x1.z * v4.z + x1.w * v4.w;
        float d2 = x2.x * v4.x + x2.y * v4.y + x2.z * v4.z + x2.w * v4.w;
        float d3 = x3.x * v4.x + x3.y * v4.y + x3.z * v4.z + x3.w * v4.w;
        float d4 = x4.x * v4.x + x4.y * v4.y + x4.z * v4.z + x4.w * v4.w;
        float d5 = x5.x * v4.x + x5.y * v4.y + x5.z * v4.z + x5.w * v4.w;
        float d6 = x6.x * v4.x + x6.y * v4.y + x6.z * v4.z + x6.w * v4.w;
        float d7 = x7.x * v4.x + x7.y * v4.y + x7.z * v4.z + x7.w * v4.w;

        // merge tree: 8 values -> 1 per lane group. 9 SHFLs total.
        float e0 = merge2(d0, d1, lane, 16);
        float e1 = merge2(d2, d3, lane, 16);
        float e2 = merge2(d4, d5, lane, 16);
        float e3 = merge2(d6, d7, lane, 16);
        float f0 = merge2(e0, e1, lane, 8);
        float f1 = merge2(e2, e3, lane, 8);
        float gg = merge2(f0, f1, lane, 4);
        gg += __shfl_xor_sync(0xffffffffu, gg, 2);
        gg += __shfl_xor_sync(0xffffffffu, gg, 1);
        // lane now holds full dot for j = j0 + k + idx (4 lanes per value)

        float nb = __shfl_sync(0xffffffffu, nbv, k + idx);
        float p  = __expf(gg + nb);
        if ((lane & 3) == 0) {
            sp[j0 + k + idx] = p;
            wsum += p;
        }
    }
    // 8 storing lanes hold distinct values; others carry 0
    #pragma unroll
    for (int o = 16; o > 0; o >>= 1)
        wsum += __shfl_xor_sync(0xffffffffu, wsum, o);
    if (lane == 0) sred[w] = wsum;
    __syncthreads();   // single barrier

    float ss = sred[lane];
    #pragma unroll
    for (int o = 16; o > 0; o >>= 1)
        ss += __shfl_xor_sync(0xffffffffu, ss, o);

    __stcs(&out[(size_t)i * N + tid], sp[tid] * (1.0f / ss));
}

// ---------------------------------------------------------------------------
// Launcher. Input order per metadata:
// 0 node_feat (N,D) f32 | 1 edge_feat (N,N,D) f32 | 2 mask (unused)
// 3 Wh | 4 bh | 5 Wt | 6 bt | 7 Wr | 8 br | 9 wt_w | 10 wt_b
// (bh/bt/br/wt_b unused: they shift all energies equally -> cancel in softmax)
// ---------------------------------------------------------------------------
extern "C" void kernel_launch(void* const* d_in, const int* in_sizes, int n_in,
                              void* d_out, int out_size) {
    const float* node_feat = (const float*)d_in[0];
    const float* edge_feat = (const float*)d_in[1];
    const float* Wh   = (const float*)d_in[3];
    const float* Wt   = (const float*)d_in[5];
    const float* Wr   = (const float*)d_in[7];
    const float* wt_w = (const float*)d_in[9];
    float* out = (float*)d_out;

    prologue_kernel<<<64, 1024>>>(node_feat, Wh, Wt, Wr, wt_w);
    main_kernel<<<N, 1024>>>(edge_feat, out);
}

// round 14
// speedup vs baseline: 1.1724x; 1.0497x over previous
#include <cuda_runtime.h>
#include <cuda_bf16.h>

#define N 1024
#define D 128
#define H 128

// Scratch (allocation-free rule: __device__ globals)
__device__ __align__(16) float g_v[D];   // reduced v
__device__ float g_nb[N];                // node_part[j] (consts cancel in softmax)

// ---------------------------------------------------------------------------
// Prologue (fused setup + nodepart). 64 blocks x 1024 threads. (R13 shape)
// ---------------------------------------------------------------------------
__global__ void __launch_bounds__(1024, 1)
prologue_kernel(const float* __restrict__ node_feat,
                const float* __restrict__ Wh,
                const float* __restrict__ Wt,
                const float* __restrict__ Wr,
                const float* __restrict__ wt_w) {
    const int tid  = threadIdx.x;
    const int d    = tid & 127;
    const int g    = tid >> 7;      // 0..7
    const int lane = tid & 31;
    const int w    = tid >> 5;      // warp 0..31

    __shared__ float su[8][128];
    __shared__ float sv[8][128];

    // prefetch node_feat row for nb warps (independent of weight loads)
    float4 x = make_float4(0.f, 0.f, 0.f, 0.f);
    const int j = blockIdx.x * 16 + w;
    if (w < 16) {
        x = reinterpret_cast<const float4*>(node_feat + (size_t)j * D)[lane];
    }

    float u = 0.f, v = 0.f;
    const int h0 = g * 16;
    #pragma unroll
    for (int k = 0; k < 16; ++k) {
        int h = h0 + k;
        float w1 = __ldg(&wt_w[h]);
        float w2 = __ldg(&wt_w[H + h]);
        float w3 = __ldg(&wt_w[2 * H + h]);
        u = fmaf(__ldg(&Wh[h * D + d]), w1, u);
        u = fmaf(__ldg(&Wt[h * D + d]), w2, u);
        v = fmaf(__ldg(&Wr[h * D + d]), w3, v);
    }
    su[g][d] = u;
    sv[g][d] = v;
    __syncthreads();

    if (blockIdx.x == 0 && tid < 128) {
        float vv = 0.f;
        #pragma unroll
        for (int gg = 0; gg < 8; ++gg) vv += sv[gg][tid];
        g_v[tid] = vv;
    }

    if (w < 16) {
        float4 u4 = make_float4(0.f, 0.f, 0.f, 0.f);
        #pragma unroll
        for (int gg = 0; gg < 8; ++gg) {
            float4 p = reinterpret_cast<const float4*>(su[gg])[lane];
            u4.x += p.x; u4.y += p.y; u4.z += p.z; u4.w += p.w;
        }
        float dsum = x.x * u4.x + x.y * u4.y + x.z * u4.z + x.w * u4.w;
        #pragma unroll
        for (int o = 16; o > 0; o >>= 1)
            dsum += __shfl_xor_sync(0xffffffffu, dsum, o);
        if (lane == 0) g_nb[j] = dsum;
    }
}

// Merge two distributed partial sums across lane groups.
__device__ __forceinline__ float merge2(float a, float b, int lane, int bit) {
    float t = (lane & bit) ? a : b;
    float u = __shfl_xor_sync(0xffffffffu, t, bit);
    return ((lane & bit) ? b : a) + u;
}

struct Batch {
    float4 x0, x1, x2, x3, x4, x5, x6, x7;
};

__device__ __forceinline__ Batch load_batch(const float4* __restrict__ base,
                                            int j0, int k, int lane) {
    Batch b;
    b.x0 = __ldcs(&base[(size_t)(j0 + k + 0) * (D / 4) + lane]);
    b.x1 = __ldcs(&base[(size_t)(j0 + k + 1) * (D / 4) + lane]);
    b.x2 = __ldcs(&base[(size_t)(j0 + k + 2) * (D / 4) + lane]);
    b.x3 = __ldcs(&base[(size_t)(j0 + k + 3) * (D / 4) + lane]);
    b.x4 = __ldcs(&base[(size_t)(j0 + k + 4) * (D / 4) + lane]);
    b.x5 = __ldcs(&base[(size_t)(j0 + k + 5) * (D / 4) + lane]);
    b.x6 = __ldcs(&base[(size_t)(j0 + k + 6) * (D / 4) + lane]);
    b.x7 = __ldcs(&base[(size_t)(j0 + k + 7) * (D / 4) + lane]);
    return b;
}

__device__ __forceinline__ void process_batch(const Batch& b, float4 v4,
                                              int j0, int k, int lane, int idx,
                                              float nbv,
                                              float* __restrict__ sp,
                                              float& wsum) {
    float d0 = b.x0.x * v4.x + b.x0.y * v4.y + b.x0.z * v4.z + b.x0.w * v4.w;
    float d1 = b.x1.x * v4.x + b.x1.y * v4.y + b.x1.z * v4.z + b.x1.w * v4.w;
    float d2 = b.x2.x * v4.x + b.x2.y * v4.y + b.x2.z * v4.z + b.x2.w * v4.w;
    float d3 = b.x3.x * v4.x + b.x3.y * v4.y + b.x3.z * v4.z + b.x3.w * v4.w;
    float d4 = b.x4.x * v4.x + b.x4.y * v4.y + b.x4.z * v4.z + b.x4.w * v4.w;
    float d5 = b.x5.x * v4.x + b.x5.y * v4.y + b.x5.z * v4.z + b.x5.w * v4.w;
    float d6 = b.x6.x * v4.x + b.x6.y * v4.y + b.x6.z * v4.z + b.x6.w * v4.w;
    float d7 = b.x7.x * v4.x + b.x7.y * v4.y + b.x7.z * v4.z + b.x7.w * v4.w;

    // merge tree: 8 values -> 1 per lane group. 9 SHFLs total.
    float e0 = merge2(d0, d1, lane, 16);
    float e1 = merge2(d2, d3, lane, 16);
    float e2 = merge2(d4, d5, lane, 16);
    float e3 = merge2(d6, d7, lane, 16);
    float f0 = merge2(e0, e1, lane, 8);
    float f1 = merge2(e2, e3, lane, 8);
    float gg = merge2(f0, f1, lane, 4);
    gg += __shfl_xor_sync(0xffffffffu, gg, 2);
    gg += __shfl_xor_sync(0xffffffffu, gg, 1);
    // lane holds full dot for j = j0 + k + idx (4 lanes per value)

    float nb = __shfl_sync(0xffffffffu, nbv, k + idx);
    float p  = __expf(gg + nb);
    if ((lane & 3) == 0) {
        sp[j0 + k + idx] = p;
        wsum += p;
    }
}

// ---------------------------------------------------------------------------
// Main: converged streaming shape (one block per row, 1024 threads,
// grid=1024). PDL version: batch-0 loads (independent of prologue outputs)
// issue BEFORE cudaGridDependencySynchronize(); v/nb load after. This lets
// main's blocks start during the prologue and the launch gap.
// ---------------------------------------------------------------------------
__global__ void __launch_bounds__(1024, 1)
main_kernel(const float* __restrict__ edge_feat, float* __restrict__ out) {
    const int i    = blockIdx.x;
    const int tid  = threadIdx.x;
    const int lane = tid & 31;
    const int w    = tid >> 5;

    __shared__ float sp[N];      // exp(energy)
    __shared__ float sred[32];

    const float4* base =
        reinterpret_cast<const float4*>(edge_feat + (size_t)i * N * D);
    const int j0 = w << 5;
    const int idx = (((lane >> 2) & 1) << 2) | (((lane >> 3) & 1) << 1)
                  | ((lane >> 4) & 1);

    // batch 0: loads in flight before the dependency sync
    Batch b0 = load_batch(base, j0, 0, lane);

#if __CUDA_ARCH__ >= 900
    cudaGridDependencySynchronize();
#endif

    const float4 v4  = reinterpret_cast<const float4*>(g_v)[lane];
    const float nbv  = g_nb[j0 + lane];

    float wsum = 0.f;
    process_batch(b0, v4, j0, 0, lane, idx, nbv, sp, wsum);
    #pragma unroll
    for (int k = 8; k < 32; k += 8) {
        Batch b = load_batch(base, j0, k, lane);
        process_batch(b, v4, j0, k, lane, idx, nbv, sp, wsum);
    }

    #pragma unroll
    for (int o = 16; o > 0; o >>= 1)
        wsum += __shfl_xor_sync(0xffffffffu, wsum, o);
    if (lane == 0) sred[w] = wsum;
    __syncthreads();   // single barrier

    float ss = sred[lane];
    #pragma unroll
    for (int o = 16; o > 0; o >>= 1)
        ss += __shfl_xor_sync(0xffffffffu, ss, o);

    __stcs(&out[(size_t)i * N + tid], sp[tid] * (1.0f / ss));
}

// ---------------------------------------------------------------------------
// Launcher. Input order per metadata:
// 0 node_feat (N,D) f32 | 1 edge_feat (N,N,D) f32 | 2 mask (unused)
// 3 Wh | 4 bh | 5 Wt | 6 bt | 7 Wr | 8 br | 9 wt_w | 10 wt_b
// (bh/bt/br/wt_b unused: uniform shifts cancel in softmax)
// ---------------------------------------------------------------------------
extern "C" void kernel_launch(void* const* d_in, const int* in_sizes, int n_in,
                              void* d_out, int out_size) {
    const float* node_feat = (const float*)d_in[0];
    const float* edge_feat = (const float*)d_in[1];
    const float* Wh   = (const float*)d_in[3];
    const float* Wt   = (const float*)d_in[5];
    const float* Wr   = (const float*)d_in[7];
    const float* wt_w = (const float*)d_in[9];
    float* out = (float*)d_out;

    prologue_kernel<<<64, 1024>>>(node_feat, Wh, Wt, Wr, wt_w);

    // PDL launch: main starts while prologue drains; it syncs via
    // cudaGridDependencySynchronize() before touching g_v/g_nb.
    cudaLaunchAttribute attrs[1];
    attrs[0].id = cudaLaunchAttributeProgrammaticStreamSerialization;
    attrs[0].val.programmaticStreamSerializationAllowed = 1;

    cudaLaunchConfig_t cfg = {};
    cfg.gridDim  = dim3(N, 1, 1);
    cfg.blockDim = dim3(1024, 1, 1);
    cfg.dynamicSmemBytes = 0;
    cfg.stream = 0;
    cfg.attrs = attrs;
    cfg.numAttrs = 1;

    cudaError_t err = cudaLaunchKernelEx(&cfg, main_kernel, edge_feat, out);
    if (err != cudaSuccess) {
        // fallback: plain serialized launch (still correct)
        main_kernel<<<N, 1024>>>(edge_feat, out);
    }
}